// round 5
// baseline (speedup 1.0000x reference)
#include <cuda_runtime.h>
#include <cuda_pipeline.h>

#define BB 4
#define CC 64
#define HH 128
#define WW 416
#define HW (HH*WW)
#define CHW (CC*HH*WW)

// Scratch for warped x2 (no cudaMalloc allowed)
__device__ float g_x2w[(size_t)BB*CHW];

__device__ __forceinline__ float lrelu(float v) { return v >= 0.f ? v : 0.1f*v; }

// ---- packed f32x2 helpers (Blackwell FMA pipe: 2 MACs per slot) ----------
typedef unsigned long long u64;
__device__ __forceinline__ u64 pk2(float lo, float hi) {
    u64 r; asm("mov.b64 %0, {%1, %2};" : "=l"(r) : "f"(lo), "f"(hi)); return r;
}
__device__ __forceinline__ void fma2(u64& d, u64 a, u64 b) {
    asm("fma.rn.f32x2 %0, %1, %2, %0;" : "+l"(d) : "l"(a), "l"(b));
}
__device__ __forceinline__ float2 up2(u64 v) {
    float2 f; asm("mov.b64 {%0, %1}, %2;" : "=f"(f.x), "=f"(f.y) : "l"(v)); return f;
}

// ===========================================================================
// Kernel 1: bilinear warp of x2 -> g_x2w. Per-thread weights/indices hoisted,
// 32 pure-gather iterations per thread, MLP via unroll.
// ===========================================================================
__global__ __launch_bounds__(208)
void warp_kernel(const float* __restrict__ x2, const float* __restrict__ flow) {
    const int xi = threadIdx.x;        // 0..103
    const int ty = threadIdx.y;        // 0..1
    const int x0t = blockIdx.x * 104;
    const int y = blockIdx.y, b = blockIdx.z;
    const int x = x0t + xi;

    const float fx = flow[((size_t)(b*2+0)*HH + y)*WW + x];
    const float fy = flow[((size_t)(b*2+1)*HH + y)*WW + x];
    const float gx = (float)x + fx;
    const float gy = (float)y + fy;
    const float x0f = floorf(gx), y0f = floorf(gy);
    const float wx = gx - x0f, wy = gy - y0f;
    const int x0 = (int)x0f, y0 = (int)y0f;
    const int x1i = x0 + 1,  y1i = y0 + 1;

    const float vx0 = (x0  >= 0 && x0  < WW) ? 1.f : 0.f;
    const float vx1 = (x1i >= 0 && x1i < WW) ? 1.f : 0.f;
    const float vy0 = (y0  >= 0 && y0  < HH) ? 1.f : 0.f;
    const float vy1 = (y1i >= 0 && y1i < HH) ? 1.f : 0.f;

    const int x0c = min(max(x0, 0), WW-1);
    const int x1c = min(max(x1i,0), WW-1);
    const int y0c = min(max(y0, 0), HH-1);
    const int y1c = min(max(y1i,0), HH-1);

    const float w00 = (1.f-wx)*(1.f-wy)*vx0*vy0;
    const float w01 = wx*(1.f-wy)*vx1*vy0;
    const float w10 = (1.f-wx)*wy*vx0*vy1;
    const float w11 = wx*wy*vx1*vy1;
    const int i00 = y0c*WW + x0c;
    const int i01 = y0c*WW + x1c;
    const int i10 = y1c*WW + x0c;
    const int i11 = y1c*WW + x1c;

    const float* xb = x2 + (size_t)b*CHW;
    float* ob = g_x2w + (size_t)b*CHW + (size_t)y*WW + x;
#pragma unroll 4
    for (int c = ty; c < CC; c += 2) {
        const float* p = xb + (size_t)c*HW;
        ob[(size_t)c*HW] = w00*__ldg(p+i00) + w01*__ldg(p+i01)
                         + w10*__ldg(p+i10) + w11*__ldg(p+i11);
    }
}

// ===========================================================================
// Kernel 2: 192-ch disparity cost volume (f32x2 inner loop)
// Thread: dg = t/26 (0..11), xg = t%26; tile 16 d x 4 x per thread.
// ===========================================================================
#define TXD 104
#define RWD 296
#define CTD 16
#define NTD (CC/CTD)
#define DISP_BUF (CTD*TXD + CTD*RWD)    // 6400 floats
#define DSP_SMEM (2*DISP_BUF*4)         // 51200 B

__global__ __launch_bounds__(320)
void disp_kernel(const float* __restrict__ x1, const float* __restrict__ r1,
                 float* __restrict__ out) {
    extern __shared__ float sm[];
    const int y = blockIdx.y, b = blockIdx.z;
    const int t = threadIdx.x;
    const int x0t = blockIdx.x * TXD;
    const int dg = t / 26;
    const int xg = t - dg*26;
    const bool act = (t < 312);

    const float* x1p = x1 + (size_t)b*CHW + (size_t)y*WW + x0t;
    const float* rp  = r1 + (size_t)b*CHW + (size_t)y*WW;

    u64 acc[16][2];
#pragma unroll
    for (int i = 0; i < 16; i++) { acc[i][0] = 0ull; acc[i][1] = 0ull; }

    auto load_tile = [&](int bi, int kt) {
        float* da = sm + bi*DISP_BUF;
        float* dr = da + CTD*TXD;
        const int ct = kt * CTD;
#pragma unroll
        for (int i = t; i < CTD*26; i += 320) {
            int c = i / 26, x4 = (i - 26*c) * 4;
            __pipeline_memcpy_async(da + c*TXD + x4,
                                    x1p + (size_t)(ct+c)*HW + x4, 16);
        }
#pragma unroll
        for (int i = t; i < CTD*74; i += 320) {
            int c = i / 74, x4 = (i - 74*c) * 4;
            int gx = x0t - 96 + x4;
            float* dst = dr + c*RWD + x4;
            if ((unsigned)gx < WW)
                __pipeline_memcpy_async(dst, rp + (size_t)(ct+c)*HW + gx, 16);
            else
                *reinterpret_cast<float4*>(dst) = make_float4(0.f,0.f,0.f,0.f);
        }
    };

    load_tile(0, 0);
    __pipeline_commit();

    for (int k = 0; k < NTD; k++) {
        if (k + 1 < NTD) {
            load_tile((k+1) & 1, k+1);
            __pipeline_commit();
            __pipeline_wait_prior(1);
        } else {
            __pipeline_wait_prior(0);
        }
        __syncthreads();

        if (act) {
            const float* da = sm + (k&1)*DISP_BUF;
            const float* ap = da + xg*4;
            const float* bp = da + CTD*TXD + xg*4 + dg*16;
#pragma unroll 4
            for (int c = 0; c < CTD; c++) {
                const float4 a = *reinterpret_cast<const float4*>(ap + c*TXD);
                const u64 a01 = pk2(a.x, a.y);
                const u64 a23 = pk2(a.z, a.w);
                const float4 q0 = *reinterpret_cast<const float4*>(bp + c*RWD);
                const float4 q1 = *reinterpret_cast<const float4*>(bp + c*RWD + 4);
                const float4 q2 = *reinterpret_cast<const float4*>(bp + c*RWD + 8);
                const float4 q3 = *reinterpret_cast<const float4*>(bp + c*RWD + 12);
                const float4 q4 = *reinterpret_cast<const float4*>(bp + c*RWD + 16);
                const float bv[20] = {q0.x,q0.y,q0.z,q0.w, q1.x,q1.y,q1.z,q1.w,
                                      q2.x,q2.y,q2.z,q2.w, q3.x,q3.y,q3.z,q3.w,
                                      q4.x,q4.y,q4.z,q4.w};
                u64 pr[18];
#pragma unroll
                for (int j = 0; j < 18; j++) pr[j] = pk2(bv[j], bv[j+1]);
#pragma unroll
                for (int dj = 0; dj < 16; dj++) {
                    fma2(acc[dj][0], a01, pr[dj]);
                    fma2(acc[dj][1], a23, pr[dj+2]);
                }
            }
        }
        __syncthreads();
    }

    if (act) {
        float* op = out + ((size_t)(b*273 + 81 + dg*16)*HH + y)*WW + x0t + xg*4;
#pragma unroll
        for (int dj = 0; dj < 16; dj++) {
            const float2 lo = up2(acc[dj][0]);
            const float2 hi = up2(acc[dj][1]);
            float4 v;
            v.x = lrelu(lo.x); v.y = lrelu(lo.y);
            v.z = lrelu(hi.x); v.w = lrelu(hi.y);
            *reinterpret_cast<float4*>(op + (size_t)dj*HW) = v;
        }
    }
}

// ===========================================================================
// Kernel 3: 81-ch cost volume (f32x2, x-span 8 per thread to cut crossbar)
// Thread (t<117): dy = t/13, xg = t%13; tile 9 dx x 8 x per thread.
// ===========================================================================
#define TXC 104
#define CTC 8
#define BWC 112
#define NTC (CC/CTC)
#define CORR_BUF (CTC*TXC + 9*CTC*BWC)   // 8896 floats
#define CORR_SMEM (2*CORR_BUF*4)         // 71168 B

__global__ __launch_bounds__(128)
void corr_kernel(const float* __restrict__ x1, float* __restrict__ out) {
    extern __shared__ float sm[];

    const int x0t = blockIdx.x * TXC;
    const int y = blockIdx.y, b = blockIdx.z;
    const int t = threadIdx.x;
    const int dy = t / 13;
    const int xg = t - dy*13;
    const bool act = (t < 117);

    const float* x1p = x1 + (size_t)b*CHW + (size_t)y*WW + x0t;
    const float* wp  = g_x2w + (size_t)b*CHW;

    u64 acc[9][4];
#pragma unroll
    for (int i = 0; i < 9; i++)
#pragma unroll
        for (int j = 0; j < 4; j++) acc[i][j] = 0ull;

    auto load_tile = [&](int bi, int kt) {
        float* da = sm + bi*CORR_BUF;
        float* db = da + CTC*TXC;
        const int ct = kt * CTC;
#pragma unroll
        for (int i = t; i < CTC*26; i += 128) {
            int c = i / 26, x4 = (i - 26*c) * 4;
            __pipeline_memcpy_async(da + c*TXC + x4,
                                    x1p + (size_t)(ct+c)*HW + x4, 16);
        }
#pragma unroll
        for (int i = t; i < CTC*28; i += 128) {
            int c = i / 28, x4 = (i - 28*c) * 4;
            const int gx2 = x0t - 4 + x4;
            const bool px = ((unsigned)gx2 < WW);
            const float* srcb = wp + (size_t)(ct+c)*HW + gx2;
            float* dstb = db + c*BWC + x4;
#pragma unroll
            for (int r = 0; r < 9; r++) {
                const int gy2 = y + r - 4;
                if (px && (unsigned)gy2 < HH)
                    __pipeline_memcpy_async(dstb + r*(CTC*BWC),
                                            srcb + (size_t)gy2*WW, 16);
                else
                    *reinterpret_cast<float4*>(dstb + r*(CTC*BWC)) =
                        make_float4(0.f,0.f,0.f,0.f);
            }
        }
    };

    load_tile(0, 0);
    __pipeline_commit();

    for (int k = 0; k < NTC; k++) {
        if (k + 1 < NTC) {
            load_tile((k+1) & 1, k+1);
            __pipeline_commit();
            __pipeline_wait_prior(1);
        } else {
            __pipeline_wait_prior(0);
        }
        __syncthreads();

        if (act) {
            const float* da = sm + (k&1)*CORR_BUF;
            const float* ap = da + xg*8;
            const float* bp = da + CTC*TXC + dy*(CTC*BWC) + xg*8;
#pragma unroll 4
            for (int c = 0; c < CTC; c++) {
                const float4 A0 = *reinterpret_cast<const float4*>(ap + c*TXC);
                const float4 A1 = *reinterpret_cast<const float4*>(ap + c*TXC + 4);
                const u64 aa0 = pk2(A0.x, A0.y);
                const u64 aa1 = pk2(A0.z, A0.w);
                const u64 aa2 = pk2(A1.x, A1.y);
                const u64 aa3 = pk2(A1.z, A1.w);
                const float4 q0 = *reinterpret_cast<const float4*>(bp + c*BWC);
                const float4 q1 = *reinterpret_cast<const float4*>(bp + c*BWC + 4);
                const float4 q2 = *reinterpret_cast<const float4*>(bp + c*BWC + 8);
                const float4 q3 = *reinterpret_cast<const float4*>(bp + c*BWC + 12);
                const float bv[16] = {q0.x,q0.y,q0.z,q0.w, q1.x,q1.y,q1.z,q1.w,
                                      q2.x,q2.y,q2.z,q2.w, q3.x,q3.y,q3.z,q3.w};
                u64 pr[15];
#pragma unroll
                for (int j = 0; j < 15; j++) pr[j] = pk2(bv[j], bv[j+1]);
#pragma unroll
                for (int dx = 0; dx < 9; dx++) {
                    fma2(acc[dx][0], aa0, pr[dx]);
                    fma2(acc[dx][1], aa1, pr[dx+2]);
                    fma2(acc[dx][2], aa2, pr[dx+4]);
                    fma2(acc[dx][3], aa3, pr[dx+6]);
                }
            }
        }
        __syncthreads();
    }

    if (act) {
        float* op = out + ((size_t)(b*273 + dy*9)*HH + y)*WW + x0t + xg*8;
#pragma unroll
        for (int dx = 0; dx < 9; dx++) {
            const float2 p0 = up2(acc[dx][0]);
            const float2 p1 = up2(acc[dx][1]);
            const float2 p2 = up2(acc[dx][2]);
            const float2 p3 = up2(acc[dx][3]);
            float4 v0, v1;
            v0.x = lrelu(p0.x); v0.y = lrelu(p0.y);
            v0.z = lrelu(p1.x); v0.w = lrelu(p1.y);
            v1.x = lrelu(p2.x); v1.y = lrelu(p2.y);
            v1.z = lrelu(p3.x); v1.w = lrelu(p3.y);
            *reinterpret_cast<float4*>(op + (size_t)dx*HW)     = v0;
            *reinterpret_cast<float4*>(op + (size_t)dx*HW + 4) = v1;
        }
    }
}

// ===========================================================================
extern "C" void kernel_launch(void* const* d_in, const int* in_sizes, int n_in,
                              void* d_out, int out_size) {
    const float* x1   = (const float*)d_in[0];
    const float* x2   = (const float*)d_in[1];
    const float* r1   = (const float*)d_in[2];
    const float* flow = (const float*)d_in[3];
    float* out = (float*)d_out;

    cudaFuncSetAttribute(disp_kernel, cudaFuncAttributeMaxDynamicSharedMemorySize, DSP_SMEM);
    cudaFuncSetAttribute(corr_kernel, cudaFuncAttributeMaxDynamicSharedMemorySize, CORR_SMEM);

    warp_kernel<<<dim3(4, HH, BB), dim3(104, 2)>>>(x2, flow);
    disp_kernel<<<dim3(4, HH, BB), 320, DSP_SMEM>>>(x1, r1, out);
    corr_kernel<<<dim3(4, HH, BB), 128, CORR_SMEM>>>(x1, out);
}

// round 6
// speedup vs baseline: 1.3729x; 1.3729x over previous
#include <cuda_runtime.h>
#include <cuda_pipeline.h>

#define BB 4
#define CC 64
#define HH 128
#define WW 416
#define HW (HH*WW)
#define CHW (CC*HH*WW)

// Scratch for warped x2 (no cudaMalloc allowed)
__device__ float g_x2w[(size_t)BB*CHW];

__device__ __forceinline__ float lrelu(float v) { return v >= 0.f ? v : 0.1f*v; }

// ===========================================================================
// Fused kernel: threads 0..311  = 192-ch disparity cost volume (FMA-bound)
//               threads 312..383 = bilinear-warp filler (latency-bound,
//               overlaps the FMA warps between the pipeline barriers)
// ===========================================================================
#define TXD 104
#define RWD 296                         // 104 + 191 halo, padded to mult of 4
#define CTD 16
#define NTD (CC/CTD)                    // 4 pipeline stages
#define DISP_BUF (CTD*TXD + CTD*RWD)    // 6400 floats per buffer
#define DSP_SMEM (2*DISP_BUF*4)         // 51200 B
#define NT 384

__global__ __launch_bounds__(NT)
void fused_disp_warp(const float* __restrict__ x1, const float* __restrict__ r1,
                     const float* __restrict__ x2, const float* __restrict__ flow,
                     float* __restrict__ out) {
    extern __shared__ float sm[];
    const int y = blockIdx.y, b = blockIdx.z;
    const int t = threadIdx.x;
    const int x0t = blockIdx.x * TXD;

    const float* x1p = x1 + (size_t)b*CHW + (size_t)y*WW + x0t;
    const float* rp  = r1 + (size_t)b*CHW + (size_t)y*WW;

    // -------- disp state --------
    const int dg = t / 26;
    const int xg = t - dg*26;
    const bool act = (t < 312);

    float acc[16][4];
#pragma unroll
    for (int i = 0; i < 16; i++)
#pragma unroll
        for (int j = 0; j < 4; j++) acc[i][j] = 0.f;

    // -------- warp-filler state (threads 312..383) --------
    const int t2 = t - 312;                 // 0..71
    float w00[2], w01[2], w10[2], w11[2];
    int   i00[2], i01[2], i10[2], i11[2];
    int   npix = 0;
    const float* xb = x2 + (size_t)b*CHW;
    float* ob = g_x2w + (size_t)b*CHW + (size_t)y*WW;
    int pxx[2];
    if (!act) {
#pragma unroll
        for (int p = 0; p < 2; p++) {
            const int xi = t2 + p*72;
            if (xi < TXD) {
                const int x = x0t + xi;
                const float fx = flow[((size_t)(b*2+0)*HH + y)*WW + x];
                const float fy = flow[((size_t)(b*2+1)*HH + y)*WW + x];
                const float gx = (float)x + fx;
                const float gy = (float)y + fy;
                const float x0f = floorf(gx), y0f = floorf(gy);
                const float wx = gx - x0f, wy = gy - y0f;
                const int x0 = (int)x0f, y0 = (int)y0f;
                const int x1i = x0 + 1,  y1i = y0 + 1;
                const float vx0 = (x0  >= 0 && x0  < WW) ? 1.f : 0.f;
                const float vx1 = (x1i >= 0 && x1i < WW) ? 1.f : 0.f;
                const float vy0 = (y0  >= 0 && y0  < HH) ? 1.f : 0.f;
                const float vy1 = (y1i >= 0 && y1i < HH) ? 1.f : 0.f;
                const int x0c = min(max(x0, 0), WW-1);
                const int x1c = min(max(x1i,0), WW-1);
                const int y0c = min(max(y0, 0), HH-1);
                const int y1c = min(max(y1i,0), HH-1);
                w00[npix] = (1.f-wx)*(1.f-wy)*vx0*vy0;
                w01[npix] = wx*(1.f-wy)*vx1*vy0;
                w10[npix] = (1.f-wx)*wy*vx0*vy1;
                w11[npix] = wx*wy*vx1*vy1;
                i00[npix] = y0c*WW + x0c;
                i01[npix] = y0c*WW + x1c;
                i10[npix] = y1c*WW + x0c;
                i11[npix] = y1c*WW + x1c;
                pxx[npix] = x0t + xi;
                npix++;
            }
        }
    }

    // ---- async tile loader (all-float4; boundary f4s are all-in or all-out)
    auto load_tile = [&](int bi, int kt) {
        float* da = sm + bi*DISP_BUF;
        float* dr = da + CTD*TXD;
        const int ct = kt * CTD;
#pragma unroll
        for (int i = t; i < CTD*26; i += NT) {
            int c = i / 26, x4 = (i - 26*c) * 4;
            __pipeline_memcpy_async(da + c*TXD + x4,
                                    x1p + (size_t)(ct+c)*HW + x4, 16);
        }
#pragma unroll
        for (int i = t; i < CTD*74; i += NT) {
            int c = i / 74, x4 = (i - 74*c) * 4;
            int gx = x0t - 96 + x4;
            float* dst = dr + c*RWD + x4;
            if ((unsigned)gx < WW)
                __pipeline_memcpy_async(dst, rp + (size_t)(ct+c)*HW + gx, 16);
            else
                *reinterpret_cast<float4*>(dst) = make_float4(0.f,0.f,0.f,0.f);
        }
    };

    load_tile(0, 0);
    __pipeline_commit();

    for (int k = 0; k < NTD; k++) {
        if (k + 1 < NTD) {
            load_tile((k+1) & 1, k+1);
            __pipeline_commit();
            __pipeline_wait_prior(1);
        } else {
            __pipeline_wait_prior(0);
        }
        __syncthreads();

        if (act) {
            const float* da = sm + (k&1)*DISP_BUF;
            const float* ap = da + xg*4;
            const float* bp = da + CTD*TXD + xg*4 + dg*16;
#pragma unroll 4
            for (int c = 0; c < CTD; c++) {
                const float4 a  = *reinterpret_cast<const float4*>(ap + c*TXD);
                const float4 q0 = *reinterpret_cast<const float4*>(bp + c*RWD);
                const float4 q1 = *reinterpret_cast<const float4*>(bp + c*RWD + 4);
                const float4 q2 = *reinterpret_cast<const float4*>(bp + c*RWD + 8);
                const float4 q3 = *reinterpret_cast<const float4*>(bp + c*RWD + 12);
                const float4 q4 = *reinterpret_cast<const float4*>(bp + c*RWD + 16);
                const float bv[20] = {q0.x,q0.y,q0.z,q0.w, q1.x,q1.y,q1.z,q1.w,
                                      q2.x,q2.y,q2.z,q2.w, q3.x,q3.y,q3.z,q3.w,
                                      q4.x,q4.y,q4.z,q4.w};
#pragma unroll
                for (int dj = 0; dj < 16; dj++) {
                    acc[dj][0] += a.x*bv[dj+0];
                    acc[dj][1] += a.y*bv[dj+1];
                    acc[dj][2] += a.z*bv[dj+2];
                    acc[dj][3] += a.w*bv[dj+3];
                }
            }
        } else {
            // warp filler: 16 channels per k-iteration, per owned pixel
#pragma unroll
            for (int p = 0; p < 2; p++) {
                if (p < npix) {
                    float* obp = ob + pxx[p];
#pragma unroll 4
                    for (int c = k*16; c < k*16 + 16; c++) {
                        const float* sp = xb + (size_t)c*HW;
                        obp[(size_t)c*HW] =
                              w00[p]*__ldg(sp+i00[p]) + w01[p]*__ldg(sp+i01[p])
                            + w10[p]*__ldg(sp+i10[p]) + w11[p]*__ldg(sp+i11[p]);
                    }
                }
            }
        }
        __syncthreads();
    }

    if (act) {
        float* op = out + ((size_t)(b*273 + 81 + dg*16)*HH + y)*WW + x0t + xg*4;
#pragma unroll
        for (int dj = 0; dj < 16; dj++) {
            float4 v;
            v.x = lrelu(acc[dj][0]);
            v.y = lrelu(acc[dj][1]);
            v.z = lrelu(acc[dj][2]);
            v.w = lrelu(acc[dj][3]);
            *reinterpret_cast<float4*>(op + (size_t)dj*HW) = v;
        }
    }
}

// ===========================================================================
// 81-channel cost volume  out[b, dy*9+dx, y, x] =
//   lrelu( sum_c x1[b,c,y,x] * x2w[b,c,y+dy-4,x+dx-4] ),  zero padded.
// CTC=4 -> 35.6 KB smem total -> 3 resident blocks (reg-limited).
// ===========================================================================
#define TXC 104
#define CTC 4
#define BWC 112                          // 104 + 8 halo
#define NTC (CC/CTC)                     // 16 pipeline stages
#define CORR_BUF (CTC*TXC + 9*CTC*BWC)   // 4448 floats per buffer
#define CORR_SMEM (2*CORR_BUF*4)         // 35584 B

__global__ __launch_bounds__(256)
void corr_kernel(const float* __restrict__ x1, float* __restrict__ out) {
    extern __shared__ float sm[];

    const int x0t = blockIdx.x * TXC;
    const int y = blockIdx.y, b = blockIdx.z;
    const int t = threadIdx.x;
    const int dy = t / 26;
    const int xg = t - dy*26;
    const bool act = (t < 234);

    const float* x1p = x1 + (size_t)b*CHW + (size_t)y*WW + x0t;
    const float* wp  = g_x2w + (size_t)b*CHW;

    // per-thread load indices, hoisted out of the stage loop
    const int ca = t / 26, xa = (t - 26*ca) * 4;          // s_a: 104 f4, t<104
    const int cb = t / 28, xb4 = (t - 28*cb) * 4;         // s_b: 112 f4 per row
    const int gx2 = x0t - 4 + xb4;
    const bool px = ((unsigned)gx2 < WW);

    float acc[9][4];
#pragma unroll
    for (int i = 0; i < 9; i++)
#pragma unroll
        for (int j = 0; j < 4; j++) acc[i][j] = 0.f;

    auto load_tile = [&](int bi, int kt) {
        float* da = sm + bi*CORR_BUF;
        float* db = da + CTC*TXC;
        const int ct = kt * CTC;
        if (t < CTC*26)
            __pipeline_memcpy_async(da + ca*TXC + xa,
                                    x1p + (size_t)(ct+ca)*HW + xa, 16);
        if (t < CTC*28) {
            const float* srcb = wp + (size_t)(ct+cb)*HW + gx2;
            float* dstb = db + cb*BWC + xb4;
#pragma unroll
            for (int r = 0; r < 9; r++) {
                const int gy2 = y + r - 4;
                if (px && (unsigned)gy2 < HH)
                    __pipeline_memcpy_async(dstb + r*(CTC*BWC),
                                            srcb + (size_t)gy2*WW, 16);
                else
                    *reinterpret_cast<float4*>(dstb + r*(CTC*BWC)) =
                        make_float4(0.f,0.f,0.f,0.f);
            }
        }
    };

    load_tile(0, 0);
    __pipeline_commit();

    for (int k = 0; k < NTC; k++) {
        if (k + 1 < NTC) {
            load_tile((k+1) & 1, k+1);
            __pipeline_commit();
            __pipeline_wait_prior(1);
        } else {
            __pipeline_wait_prior(0);
        }
        __syncthreads();

        if (act) {
            const float* da = sm + (k&1)*CORR_BUF;
            const float* ap = da + xg*4;
            const float* bp = da + CTC*TXC + dy*(CTC*BWC) + xg*4;
#pragma unroll
            for (int c = 0; c < CTC; c++) {
                const float4 a  = *reinterpret_cast<const float4*>(ap + c*TXC);
                const float4 q0 = *reinterpret_cast<const float4*>(bp + c*BWC);
                const float4 q1 = *reinterpret_cast<const float4*>(bp + c*BWC + 4);
                const float4 q2 = *reinterpret_cast<const float4*>(bp + c*BWC + 8);
                const float bv[12] = {q0.x,q0.y,q0.z,q0.w, q1.x,q1.y,q1.z,q1.w,
                                      q2.x,q2.y,q2.z,q2.w};
#pragma unroll
                for (int dx = 0; dx < 9; dx++) {
                    acc[dx][0] += a.x*bv[dx+0];
                    acc[dx][1] += a.y*bv[dx+1];
                    acc[dx][2] += a.z*bv[dx+2];
                    acc[dx][3] += a.w*bv[dx+3];
                }
            }
        }
        __syncthreads();
    }

    if (act) {
        float* op = out + ((size_t)(b*273 + dy*9)*HH + y)*WW + x0t + xg*4;
#pragma unroll
        for (int dx = 0; dx < 9; dx++) {
            float4 v;
            v.x = lrelu(acc[dx][0]);
            v.y = lrelu(acc[dx][1]);
            v.z = lrelu(acc[dx][2]);
            v.w = lrelu(acc[dx][3]);
            *reinterpret_cast<float4*>(op + (size_t)dx*HW) = v;
        }
    }
}

// ===========================================================================
extern "C" void kernel_launch(void* const* d_in, const int* in_sizes, int n_in,
                              void* d_out, int out_size) {
    const float* x1   = (const float*)d_in[0];
    const float* x2   = (const float*)d_in[1];
    const float* r1   = (const float*)d_in[2];
    const float* flow = (const float*)d_in[3];
    float* out = (float*)d_out;

    cudaFuncSetAttribute(fused_disp_warp, cudaFuncAttributeMaxDynamicSharedMemorySize, DSP_SMEM);
    cudaFuncSetAttribute(corr_kernel, cudaFuncAttributeMaxDynamicSharedMemorySize, CORR_SMEM);

    fused_disp_warp<<<dim3(4, HH, BB), NT, DSP_SMEM>>>(x1, r1, x2, flow, out);
    corr_kernel<<<dim3(WW/TXC, HH, BB), 256, CORR_SMEM>>>(x1, out);
}

// round 7
// speedup vs baseline: 1.6002x; 1.1655x over previous
#include <cuda_runtime.h>
#include <cuda_pipeline.h>

#define BB 4
#define CC 64
#define HH 128
#define WW 416
#define HW (HH*WW)
#define CHW (CC*HH*WW)

// Scratch for warped x2 (no cudaMalloc allowed)
__device__ float g_x2w[(size_t)BB*CHW];

__device__ __forceinline__ float lrelu(float v) { return v >= 0.f ? v : 0.1f*v; }

// ===========================================================================
// Fused kernel: blocks x=0..7  = 192-ch disparity cost volume (FMA-bound)
//               block  x=8     = bilinear warp of one full row (filler)
// 12d x 4x per thread, 208 active compute threads, 3 blocks/SM.
// ===========================================================================
#define TXD 52
#define RWD 244                         // 52 + 191 halo, padded to mult of 4
#define CTD 16
#define NTD (CC/CTD)                    // 4 pipeline stages
#define DISP_BUF (CTD*TXD + CTD*RWD)    // 4736 floats per buffer
#define DSP_SMEM (2*DISP_BUF*4)         // 37888 B

__global__ __launch_bounds__(256, 3)
void fused_disp_warp(const float* __restrict__ x1, const float* __restrict__ r1,
                     const float* __restrict__ x2, const float* __restrict__ flow,
                     float* __restrict__ out) {
    extern __shared__ float sm[];
    const int y = blockIdx.y, b = blockIdx.z;
    const int t = threadIdx.x;

    if (blockIdx.x == 8) {
        // ------------------ warp path: whole row y of batch b ---------------
        float* s_w = sm;                  // [4][WW]
        int*   s_i = (int*)(sm + 4*WW);   // [4][WW]
        for (int xi = t; xi < WW; xi += 256) {
            const float fx = flow[((size_t)(b*2+0)*HH + y)*WW + xi];
            const float fy = flow[((size_t)(b*2+1)*HH + y)*WW + xi];
            const float gx = (float)xi + fx;
            const float gy = (float)y + fy;
            const float x0f = floorf(gx), y0f = floorf(gy);
            const float wx = gx - x0f, wy = gy - y0f;
            const int x0 = (int)x0f, y0 = (int)y0f;
            const int x1i = x0 + 1,  y1i = y0 + 1;
            const float vx0 = (x0  >= 0 && x0  < WW) ? 1.f : 0.f;
            const float vx1 = (x1i >= 0 && x1i < WW) ? 1.f : 0.f;
            const float vy0 = (y0  >= 0 && y0  < HH) ? 1.f : 0.f;
            const float vy1 = (y1i >= 0 && y1i < HH) ? 1.f : 0.f;
            const int x0c = min(max(x0, 0), WW-1);
            const int x1c = min(max(x1i,0), WW-1);
            const int y0c = min(max(y0, 0), HH-1);
            const int y1c = min(max(y1i,0), HH-1);
            s_w[0*WW+xi] = (1.f-wx)*(1.f-wy)*vx0*vy0;
            s_w[1*WW+xi] = wx*(1.f-wy)*vx1*vy0;
            s_w[2*WW+xi] = (1.f-wx)*wy*vx0*vy1;
            s_w[3*WW+xi] = wx*wy*vx1*vy1;
            s_i[0*WW+xi] = y0c*WW + x0c;
            s_i[1*WW+xi] = y0c*WW + x1c;
            s_i[2*WW+xi] = y1c*WW + x0c;
            s_i[3*WW+xi] = y1c*WW + x1c;
        }
        __syncthreads();

        const float* xb = x2 + (size_t)b*CHW;
        float* ob = g_x2w + (size_t)b*CHW + (size_t)y*WW;
#pragma unroll 2
        for (int c = 0; c < CC; c++) {
            const float* p = xb + (size_t)c*HW;
            float* o = ob + (size_t)c*HW;
            for (int xi = t; xi < WW; xi += 256) {
                o[xi] = s_w[0*WW+xi]*__ldg(p+s_i[0*WW+xi])
                      + s_w[1*WW+xi]*__ldg(p+s_i[1*WW+xi])
                      + s_w[2*WW+xi]*__ldg(p+s_i[2*WW+xi])
                      + s_w[3*WW+xi]*__ldg(p+s_i[3*WW+xi]);
            }
        }
        return;
    }

    // ------------------ disparity path ------------------
    const int x0t = blockIdx.x * TXD;
    const int dg = t / 13;               // 0..15
    const int xg = t - dg*13;            // 0..12
    const bool act = (t < 208);

    const float* x1p = x1 + (size_t)b*CHW + (size_t)y*WW + x0t;
    const float* rp  = r1 + (size_t)b*CHW + (size_t)y*WW;

    float acc[12][4];
#pragma unroll
    for (int i = 0; i < 12; i++)
#pragma unroll
        for (int j = 0; j < 4; j++) acc[i][j] = 0.f;

    auto load_tile = [&](int bi, int kt) {
        float* da = sm + bi*DISP_BUF;
        float* dr = da + CTD*TXD;
        const int ct = kt * CTD;
        // s_a: 16 rows of 13 f4 = 208 f4
        if (t < CTD*13) {
            int c = t / 13, x4 = (t - 13*c) * 4;
            __pipeline_memcpy_async(da + c*TXD + x4,
                                    x1p + (size_t)(ct+c)*HW + x4, 16);
        }
        // s_r: 16 rows of 61 f4 = 976 f4
#pragma unroll
        for (int i = t; i < CTD*61; i += 256) {
            int c = i / 61, x4 = (i - 61*c) * 4;
            int gx = x0t - 96 + x4;
            float* dst = dr + c*RWD + x4;
            if ((unsigned)gx < WW)
                __pipeline_memcpy_async(dst, rp + (size_t)(ct+c)*HW + gx, 16);
            else
                *reinterpret_cast<float4*>(dst) = make_float4(0.f,0.f,0.f,0.f);
        }
    };

    load_tile(0, 0);
    __pipeline_commit();

    for (int k = 0; k < NTD; k++) {
        if (k + 1 < NTD) {
            load_tile((k+1) & 1, k+1);
            __pipeline_commit();
            __pipeline_wait_prior(1);
        } else {
            __pipeline_wait_prior(0);
        }
        __syncthreads();

        if (act) {
            const float* da = sm + (k&1)*DISP_BUF;
            const float* ap = da + xg*4;
            const float* bp = da + CTD*TXD + xg*4 + dg*12;
#pragma unroll 4
            for (int c = 0; c < CTD; c++) {
                const float4 a  = *reinterpret_cast<const float4*>(ap + c*TXD);
                const float4 q0 = *reinterpret_cast<const float4*>(bp + c*RWD);
                const float4 q1 = *reinterpret_cast<const float4*>(bp + c*RWD + 4);
                const float4 q2 = *reinterpret_cast<const float4*>(bp + c*RWD + 8);
                const float4 q3 = *reinterpret_cast<const float4*>(bp + c*RWD + 12);
                const float bv[16] = {q0.x,q0.y,q0.z,q0.w, q1.x,q1.y,q1.z,q1.w,
                                      q2.x,q2.y,q2.z,q2.w, q3.x,q3.y,q3.z,q3.w};
#pragma unroll
                for (int dj = 0; dj < 12; dj++) {
                    acc[dj][0] += a.x*bv[dj+0];
                    acc[dj][1] += a.y*bv[dj+1];
                    acc[dj][2] += a.z*bv[dj+2];
                    acc[dj][3] += a.w*bv[dj+3];
                }
            }
        }
        __syncthreads();
    }

    if (act) {
        float* op = out + ((size_t)(b*273 + 81 + dg*12)*HH + y)*WW + x0t + xg*4;
#pragma unroll
        for (int dj = 0; dj < 12; dj++) {
            float4 v;
            v.x = lrelu(acc[dj][0]);
            v.y = lrelu(acc[dj][1]);
            v.z = lrelu(acc[dj][2]);
            v.w = lrelu(acc[dj][3]);
            *reinterpret_cast<float4*>(op + (size_t)dj*HW) = v;
        }
    }
}

// ===========================================================================
// 81-channel cost volume  out[b, dy*9+dx, y, x] =
//   lrelu( sum_c x1[b,c,y,x] * x2w[b,c,y+dy-4,x+dx-4] ),  zero padded.
// R4 version + reg cap for 3 resident blocks.
// ===========================================================================
#define TXC 104
#define CTC 8
#define BWC 112                          // 104 + 8 halo
#define NTC (CC/CTC)                     // 8 pipeline stages
#define CORR_BUF (CTC*TXC + 9*CTC*BWC)   // 8896 floats per buffer
#define CORR_SMEM (2*CORR_BUF*4)         // 71168 B

__global__ __launch_bounds__(256, 3)
void corr_kernel(const float* __restrict__ x1, float* __restrict__ out) {
    extern __shared__ float sm[];

    const int x0t = blockIdx.x * TXC;
    const int y = blockIdx.y, b = blockIdx.z;
    const int t = threadIdx.x;
    const int dy = t / 26;
    const int xg = t - dy*26;
    const bool act = (t < 234);

    const float* x1p = x1 + (size_t)b*CHW + (size_t)y*WW + x0t;
    const float* wp  = g_x2w + (size_t)b*CHW;

    // per-thread load indices, hoisted out of the stage loop
    const int ca = t / 26, xa = (t - 26*ca) * 4;          // s_a: 208 f4, t<208
    const int cb = t / 28, xb4 = (t - 28*cb) * 4;         // s_b: 224 f4 per row
    const int gx2 = x0t - 4 + xb4;
    const bool px = ((unsigned)gx2 < WW);

    float acc[9][4];
#pragma unroll
    for (int i = 0; i < 9; i++)
#pragma unroll
        for (int j = 0; j < 4; j++) acc[i][j] = 0.f;

    auto load_tile = [&](int bi, int kt) {
        float* da = sm + bi*CORR_BUF;
        float* db = da + CTC*TXC;
        const int ct = kt * CTC;
        if (t < 208)
            __pipeline_memcpy_async(da + ca*TXC + xa,
                                    x1p + (size_t)(ct+ca)*HW + xa, 16);
        if (t < 224) {
            const float* srcb = wp + (size_t)(ct+cb)*HW + gx2;
            float* dstb = db + cb*BWC + xb4;
#pragma unroll
            for (int r = 0; r < 9; r++) {
                const int gy2 = y + r - 4;
                if (px && (unsigned)gy2 < HH)
                    __pipeline_memcpy_async(dstb + r*(CTC*BWC), srcb + gy2*WW, 16);
                else
                    *reinterpret_cast<float4*>(dstb + r*(CTC*BWC)) =
                        make_float4(0.f,0.f,0.f,0.f);
            }
        }
    };

    load_tile(0, 0);
    __pipeline_commit();

    for (int k = 0; k < NTC; k++) {
        if (k + 1 < NTC) {
            load_tile((k+1) & 1, k+1);
            __pipeline_commit();
            __pipeline_wait_prior(1);
        } else {
            __pipeline_wait_prior(0);
        }
        __syncthreads();

        if (act) {
            const float* da = sm + (k&1)*CORR_BUF;
            const float* ap = da + xg*4;
            const float* bp = da + CTC*TXC + dy*(CTC*BWC) + xg*4;
#pragma unroll
            for (int c = 0; c < CTC; c++) {
                const float4 a  = *reinterpret_cast<const float4*>(ap + c*TXC);
                const float4 q0 = *reinterpret_cast<const float4*>(bp + c*BWC);
                const float4 q1 = *reinterpret_cast<const float4*>(bp + c*BWC + 4);
                const float4 q2 = *reinterpret_cast<const float4*>(bp + c*BWC + 8);
                const float bv[12] = {q0.x,q0.y,q0.z,q0.w, q1.x,q1.y,q1.z,q1.w,
                                      q2.x,q2.y,q2.z,q2.w};
#pragma unroll
                for (int dx = 0; dx < 9; dx++) {
                    acc[dx][0] += a.x*bv[dx+0];
                    acc[dx][1] += a.y*bv[dx+1];
                    acc[dx][2] += a.z*bv[dx+2];
                    acc[dx][3] += a.w*bv[dx+3];
                }
            }
        }
        __syncthreads();
    }

    if (act) {
        float* op = out + ((size_t)(b*273 + dy*9)*HH + y)*WW + x0t + xg*4;
#pragma unroll
        for (int dx = 0; dx < 9; dx++) {
            float4 v;
            v.x = lrelu(acc[dx][0]);
            v.y = lrelu(acc[dx][1]);
            v.z = lrelu(acc[dx][2]);
            v.w = lrelu(acc[dx][3]);
            *reinterpret_cast<float4*>(op + (size_t)dx*HW) = v;
        }
    }
}

// ===========================================================================
extern "C" void kernel_launch(void* const* d_in, const int* in_sizes, int n_in,
                              void* d_out, int out_size) {
    const float* x1   = (const float*)d_in[0];
    const float* x2   = (const float*)d_in[1];
    const float* r1   = (const float*)d_in[2];
    const float* flow = (const float*)d_in[3];
    float* out = (float*)d_out;

    cudaFuncSetAttribute(fused_disp_warp, cudaFuncAttributeMaxDynamicSharedMemorySize, DSP_SMEM);
    cudaFuncSetAttribute(corr_kernel, cudaFuncAttributeMaxDynamicSharedMemorySize, CORR_SMEM);

    fused_disp_warp<<<dim3(9, HH, BB), 256, DSP_SMEM>>>(x1, r1, x2, flow, out);
    corr_kernel<<<dim3(WW/TXC, HH, BB), 256, CORR_SMEM>>>(x1, out);
}